// round 2
// baseline (speedup 1.0000x reference)
#include <cuda_runtime.h>
#include <math.h>

#define B_ 64
#define T_ 512
#define D_ 512
#define U_ 1024
#define G_ 4096   // 4*U

// Scratch (allocation-free rule: __device__ globals)
__device__ float g_xz[(size_t)B_ * T_ * G_];   // 512 MB: per-step input projections
__device__ float g_h[2][B_ * U_];              // ping-pong hidden state
__device__ float g_c[B_ * U_];                 // cell state (in-place update)

// ---------------------------------------------------------------------------
// Zero initial state (must run every kernel_launch call: graph replays)
// ---------------------------------------------------------------------------
__global__ void init_state()
{
    int idx = blockIdx.x * blockDim.x + threadIdx.x;
    if (idx < B_ * U_) {
        g_h[0][idx] = 0.0f;
        g_c[idx]    = 0.0f;
    }
}

// ---------------------------------------------------------------------------
// xz[m][n] = sum_k X[m][k] * W[k][n] + bias[n]
// M = B*T = 32768, N = 4096, K = 512
// Tile 64x64, BK=16, 256 threads, 4x4 microtile.
// ---------------------------------------------------------------------------
__global__ __launch_bounds__(256) void gemm_xz(
    const float* __restrict__ X,
    const float* __restrict__ W,
    const float* __restrict__ bias)
{
    __shared__ float As[64][20];   // [row][kk], pitch 20 floats (80B, 16B-aligned rows)
    __shared__ float Bs[16][68];   // [kk][n],  pitch 68 floats

    const int m0  = blockIdx.y * 64;
    const int n0  = blockIdx.x * 64;
    const int tid = threadIdx.x;
    const int rg  = tid >> 4;   // 0..15 -> rows 4*rg
    const int cg  = tid & 15;   // 0..15 -> cols 4*cg

    float acc[4][4] = {};

    for (int k0 = 0; k0 < D_; k0 += 16) {
        // Load A tile: 64 rows x 16 k, one float4 per thread along k
        {
            int row = tid >> 2;
            int kq  = (tid & 3) << 2;
            *(float4*)&As[row][kq] =
                *(const float4*)(X + (size_t)(m0 + row) * D_ + k0 + kq);
        }
        // Load B tile: 16 k x 64 n, one float4 per thread along n
        {
            int kk = tid >> 4;
            int nq = (tid & 15) << 2;
            *(float4*)&Bs[kk][nq] =
                *(const float4*)(W + (size_t)(k0 + kk) * G_ + n0 + nq);
        }
        __syncthreads();

        #pragma unroll
        for (int kk = 0; kk < 16; kk++) {
            float a0 = As[4*rg + 0][kk];
            float a1 = As[4*rg + 1][kk];
            float a2 = As[4*rg + 2][kk];
            float a3 = As[4*rg + 3][kk];
            float4 b = *(const float4*)&Bs[kk][4*cg];
            acc[0][0] += a0 * b.x; acc[0][1] += a0 * b.y; acc[0][2] += a0 * b.z; acc[0][3] += a0 * b.w;
            acc[1][0] += a1 * b.x; acc[1][1] += a1 * b.y; acc[1][2] += a1 * b.z; acc[1][3] += a1 * b.w;
            acc[2][0] += a2 * b.x; acc[2][1] += a2 * b.y; acc[2][2] += a2 * b.z; acc[2][3] += a2 * b.w;
            acc[3][0] += a3 * b.x; acc[3][1] += a3 * b.y; acc[3][2] += a3 * b.z; acc[3][3] += a3 * b.w;
        }
        __syncthreads();
    }

    float4 bv = *(const float4*)(bias + n0 + 4*cg);
    #pragma unroll
    for (int i = 0; i < 4; i++) {
        float4 o;
        o.x = acc[i][0] + bv.x;
        o.y = acc[i][1] + bv.y;
        o.z = acc[i][2] + bv.z;
        o.w = acc[i][3] + bv.w;
        *(float4*)(g_xz + (size_t)(m0 + 4*rg + i) * G_ + n0 + 4*cg) = o;
    }
}

// ---------------------------------------------------------------------------
// One LSTM step. Grid: 128 blocks, each owns 8 u-columns (x 4 gates = 32
// z-columns) for all 64 batch rows. Computes z_rec = h_prev @ R over K=1024
// (smem-tiled, KK=32), adds the precomputed xz slice, applies gates, updates
// c in place and writes h_next (ping-pong; last step writes d_out).
// ---------------------------------------------------------------------------
__global__ __launch_bounds__(128) void lstm_step(
    const float* __restrict__ R,
    float* __restrict__ out,
    int t)
{
    __shared__ float hs[64][36];   // [b][kk]
    __shared__ float rs[32][36];   // [kk][c]   c = gate*8 + (u - u0)
    __shared__ float zs[64][36];   // [b][c]

    const float* __restrict__ hp = g_h[t & 1];
    float* hn = (t == T_ - 1) ? out : g_h[(t + 1) & 1];

    const int u0  = blockIdx.x * 8;
    const int tid = threadIdx.x;
    const int rg  = tid >> 3;   // 0..15 -> rows 4*rg
    const int cg  = tid & 7;    // 0..7  -> cols 4*cg

    float acc[4][4] = {};

    for (int k0 = 0; k0 < U_; k0 += 32) {
        // h tile: 64 b x 32 k -> 4 float4 per thread
        #pragma unroll
        for (int q = 0; q < 4; q++) {
            int idx = tid + 128 * q;
            int row = idx >> 3;
            int kq  = (idx & 7) << 2;
            *(float4*)&hs[row][kq] =
                *(const float4*)(hp + (size_t)row * U_ + k0 + kq);
        }
        // R tile: 32 k x 32 c (4 gate groups of 8 contiguous u-cols each)
        #pragma unroll
        for (int q = 0; q < 2; q++) {
            int idx  = tid + 128 * q;
            int kk   = idx >> 3;
            int c4   = (idx & 7) << 2;                       // 0,4,...,28
            int gcol = (c4 >> 3) * U_ + u0 + (c4 & 7);       // gate*1024 + u
            *(float4*)&rs[kk][c4] =
                *(const float4*)(R + (size_t)(k0 + kk) * G_ + gcol);
        }
        __syncthreads();

        #pragma unroll
        for (int kk = 0; kk < 32; kk++) {
            float a0 = hs[4*rg + 0][kk];
            float a1 = hs[4*rg + 1][kk];
            float a2 = hs[4*rg + 2][kk];
            float a3 = hs[4*rg + 3][kk];
            float4 b = *(const float4*)&rs[kk][4*cg];
            acc[0][0] += a0 * b.x; acc[0][1] += a0 * b.y; acc[0][2] += a0 * b.z; acc[0][3] += a0 * b.w;
            acc[1][0] += a1 * b.x; acc[1][1] += a1 * b.y; acc[1][2] += a1 * b.z; acc[1][3] += a1 * b.w;
            acc[2][0] += a2 * b.x; acc[2][1] += a2 * b.y; acc[2][2] += a2 * b.z; acc[2][3] += a2 * b.w;
            acc[3][0] += a3 * b.x; acc[3][1] += a3 * b.y; acc[3][2] += a3 * b.z; acc[3][3] += a3 * b.w;
        }
        __syncthreads();
    }

    // Stash z_rec tile to smem so the gate phase can gather all 4 gates per (b,u)
    #pragma unroll
    for (int i = 0; i < 4; i++) {
        *(float4*)&zs[4*rg + i][4*cg] =
            make_float4(acc[i][0], acc[i][1], acc[i][2], acc[i][3]);
    }
    __syncthreads();

    // Gate fusion + state update: 64 b x 8 u elements, 4 per thread
    #pragma unroll
    for (int q = 0; q < 4; q++) {
        int idx = tid + 128 * q;
        int b   = idx >> 3;
        int ul  = idx & 7;
        int u   = u0 + ul;

        size_t xbase = ((size_t)b * T_ + t) * G_ + u;
        float zi = zs[b][ul]      + g_xz[xbase];
        float zf = zs[b][8  + ul] + g_xz[xbase + 1 * U_];
        float zc = zs[b][16 + ul] + g_xz[xbase + 2 * U_];
        float zo = zs[b][24 + ul] + g_xz[xbase + 3 * U_];

        float ig = 1.0f / (1.0f + expf(-zi));
        float fg = 1.0f / (1.0f + expf(-zf));
        float og = 1.0f / (1.0f + expf(-zo));

        float cn = fg * g_c[b * U_ + u] + ig * tanhf(zc);
        g_c[b * U_ + u] = cn;
        hn[b * U_ + u]  = og * tanhf(cn);
    }
}

// ---------------------------------------------------------------------------
extern "C" void kernel_launch(void* const* d_in, const int* in_sizes, int n_in,
                              void* d_out, int out_size)
{
    const float* x    = (const float*)d_in[0];   // [64, 512, 512]
    const float* W    = (const float*)d_in[1];   // [512, 4096]
    const float* R    = (const float*)d_in[2];   // [1024, 4096]
    const float* bias = (const float*)d_in[3];   // [4096]
    float* out = (float*)d_out;                  // [64, 1024]

    init_state<<<256, 256>>>();
    gemm_xz<<<dim3(G_ / 64, (B_ * T_) / 64), 256>>>(x, W, bias);
    for (int t = 0; t < T_; t++) {
        lstm_step<<<128, 128>>>(R, out, t);
    }
}

// round 7
// speedup vs baseline: 3.6972x; 3.6972x over previous
#include <cuda_runtime.h>
#include <cuda_bf16.h>
#include <math.h>
#include <stdint.h>

#define B_ 64
#define T_ 512
#define D_ 512
#define U_ 1024
#define G_ 4096   // 4*U

// ---------------------------------------------------------------------------
// Scratch (__device__ globals: allocation-free rule)
// ---------------------------------------------------------------------------
__device__ float         g_xz[(size_t)B_ * T_ * G_];     // fp32 input projections
__device__ __nv_bfloat16 g_xhi[(size_t)B_ * T_ * D_];    // x split
__device__ __nv_bfloat16 g_xlo[(size_t)B_ * T_ * D_];
__device__ __nv_bfloat16 g_Wt_hi[(size_t)G_ * D_];       // W^T split  [4096][512]
__device__ __nv_bfloat16 g_Wt_lo[(size_t)G_ * D_];
__device__ __nv_bfloat16 g_Rt_hi[(size_t)G_ * U_];       // R^T split  [4096][1024]
__device__ __nv_bfloat16 g_Rt_lo[(size_t)G_ * U_];
__device__ __nv_bfloat16 g_hhi[2][B_ * U_];              // h ping-pong, split
__device__ __nv_bfloat16 g_hlo[2][B_ * U_];
__device__ float         g_c[B_ * U_];                   // cell state

// ---------------------------------------------------------------------------
// Helpers
// ---------------------------------------------------------------------------
__device__ __forceinline__ uint32_t smem_u32(const void* p) {
    uint32_t a;
    asm("{ .reg .u64 t; cvta.to.shared.u64 t, %1; cvt.u32.u64 %0, t; }" : "=r"(a) : "l"(p));
    return a;
}
__device__ __forceinline__ uint32_t sw128(uint32_t off) { return off ^ ((off >> 3) & 0x70); }
__device__ __forceinline__ uint32_t sw64 (uint32_t off) { return off ^ ((off >> 3) & 0x30); }

#define CP16(dst, src) \
    asm volatile("cp.async.cg.shared.global [%0], [%1], 16;" :: "r"(dst), "l"(src))
#define CP_COMMIT() asm volatile("cp.async.commit_group;" ::: "memory")
#define CP_WAIT1()  asm volatile("cp.async.wait_group 1;" ::: "memory")
#define CP_WAIT0()  asm volatile("cp.async.wait_group 0;" ::: "memory")

__device__ __forceinline__ void ldsm_x4(uint32_t* r, uint32_t addr) {
    asm volatile("ldmatrix.sync.aligned.m8n8.x4.shared.b16 {%0,%1,%2,%3}, [%4];"
                 : "=r"(r[0]), "=r"(r[1]), "=r"(r[2]), "=r"(r[3]) : "r"(addr));
}
__device__ __forceinline__ void ldsm_x2(uint32_t* r, uint32_t addr) {
    asm volatile("ldmatrix.sync.aligned.m8n8.x2.shared.b16 {%0,%1}, [%2];"
                 : "=r"(r[0]), "=r"(r[1]) : "r"(addr));
}
__device__ __forceinline__ void mma16816(float* c, const uint32_t* a, const uint32_t* b) {
    asm volatile(
        "mma.sync.aligned.m16n8k16.row.col.f32.bf16.bf16.f32 "
        "{%0,%1,%2,%3}, {%4,%5,%6,%7}, {%8,%9}, {%0,%1,%2,%3};"
        : "+f"(c[0]), "+f"(c[1]), "+f"(c[2]), "+f"(c[3])
        : "r"(a[0]), "r"(a[1]), "r"(a[2]), "r"(a[3]), "r"(b[0]), "r"(b[1]));
}

// ---------------------------------------------------------------------------
// Prep kernels
// ---------------------------------------------------------------------------
__global__ void init_state()
{
    int i = blockIdx.x * blockDim.x + threadIdx.x;
    if (i < B_ * U_) {
        __nv_bfloat16 z = __float2bfloat16(0.0f);
        g_hhi[0][i] = z; g_hlo[0][i] = z;
        g_hhi[1][i] = z; g_hlo[1][i] = z;
        g_c[i] = 0.0f;
    }
}

__global__ void split_x(const float* __restrict__ x)
{
    size_t i = (size_t)blockIdx.x * blockDim.x + threadIdx.x;
    size_t n4 = (size_t)B_ * T_ * D_ / 4;
    if (i >= n4) return;
    float4 v = ((const float4*)x)[i];
    float vv[4] = {v.x, v.y, v.z, v.w};
    __nv_bfloat162* ph = (__nv_bfloat162*)g_xhi;
    __nv_bfloat162* pl = (__nv_bfloat162*)g_xlo;
    __nv_bfloat16 h[4], l[4];
    #pragma unroll
    for (int j = 0; j < 4; j++) {
        h[j] = __float2bfloat16(vv[j]);
        l[j] = __float2bfloat16(vv[j] - __bfloat162float(h[j]));
    }
    ph[2*i]     = __halves2bfloat162(h[0], h[1]);
    ph[2*i + 1] = __halves2bfloat162(h[2], h[3]);
    pl[2*i]     = __halves2bfloat162(l[0], l[1]);
    pl[2*i + 1] = __halves2bfloat162(l[2], l[3]);
}

// src [rows][cols] fp32 -> Wt/Rt [cols][rows] bf16 hi/lo.
// which=0 -> g_Wt_*, which=1 -> g_Rt_*. Destinations resolved in DEVICE code
// (passing __device__ symbols as host-side kernel args was the R4 bug).
__global__ void transpose_split_sel(const float* __restrict__ src,
                                    int which, int rows, int cols)
{
    __nv_bfloat16* dhi = which ? g_Rt_hi : g_Wt_hi;
    __nv_bfloat16* dlo = which ? g_Rt_lo : g_Wt_lo;
    __shared__ float t[32][33];
    int x = blockIdx.x * 32 + threadIdx.x;
    int y0 = blockIdx.y * 32;
    #pragma unroll
    for (int i = 0; i < 32; i += 8)
        t[threadIdx.y + i][threadIdx.x] = src[(size_t)(y0 + threadIdx.y + i) * cols + x];
    __syncthreads();
    int ox = y0 + threadIdx.x;
    #pragma unroll
    for (int i = 0; i < 32; i += 8) {
        int orow = blockIdx.x * 32 + threadIdx.y + i;
        float v = t[threadIdx.x][threadIdx.y + i];
        __nv_bfloat16 h = __float2bfloat16(v);
        dhi[(size_t)orow * rows + ox] = h;
        dlo[(size_t)orow * rows + ox] = __float2bfloat16(v - __bfloat162float(h));
    }
}

// ---------------------------------------------------------------------------
// xz = x @ W + bias via mma.sync (3-term bf16 split)
// Block tile 128m x 128n, K=512 in 16 chunks of 32 (64B rows, sw64 swizzle).
// 256 threads = 8 warps (4m x 2n); warp tile 32 x 64 (2 mfrag x 8 nfrag).
// ---------------------------------------------------------------------------
#define XAHI 0
#define XALO 8192
#define XBHI 16384
#define XBLO 24576
#define XSTG 32768   // one stage (32 KB); 2 stages = 64 KB dynamic smem

__global__ __launch_bounds__(256) void gemm_xz_mma(const float* __restrict__ bias)
{
    extern __shared__ __align__(1024) char sm[];
    uint32_t smb = smem_u32(sm);
    const int tid  = threadIdx.x;
    const int wid  = tid >> 5;
    const int lane = tid & 31;
    const int m0 = blockIdx.y * 128;
    const int n0 = blockIdx.x * 128;

    const char* xh = (const char*)g_xhi;
    const char* xl = (const char*)g_xlo;
    const char* wh = (const char*)g_Wt_hi;
    const char* wl = (const char*)g_Wt_lo;

    float acc[2][8][4] = {};

    auto issue = [&](int kc, int s) {
        uint32_t st = smb + s * XSTG;
        #pragma unroll
        for (int i = 0; i < 2; i++) {      // A hi: 128 rows x 4 granules
            int idx = tid + 256 * i;
            int r = idx >> 2, g = idx & 3;
            CP16(st + XAHI + sw64(r * 64 + g * 16),
                 xh + (size_t)(m0 + r) * 1024 + kc * 64 + g * 16);
        }
        #pragma unroll
        for (int i = 0; i < 2; i++) {      // A lo
            int idx = tid + 256 * i;
            int r = idx >> 2, g = idx & 3;
            CP16(st + XALO + sw64(r * 64 + g * 16),
                 xl + (size_t)(m0 + r) * 1024 + kc * 64 + g * 16);
        }
        #pragma unroll
        for (int i = 0; i < 2; i++) {      // B hi: 128 rows x 4 granules
            int idx = tid + 256 * i;
            int r = idx >> 2, g = idx & 3;
            CP16(st + XBHI + sw64(r * 64 + g * 16),
                 wh + (size_t)(n0 + r) * 1024 + kc * 64 + g * 16);
        }
        #pragma unroll
        for (int i = 0; i < 2; i++) {      // B lo
            int idx = tid + 256 * i;
            int r = idx >> 2, g = idx & 3;
            CP16(st + XBLO + sw64(r * 64 + g * 16),
                 wl + (size_t)(n0 + r) * 1024 + kc * 64 + g * 16);
        }
    };

    issue(0, 0); CP_COMMIT();

    const int mrow = 32 * (wid >> 1);
    const int ncol = 64 * (wid & 1);
    const int mi  = lane >> 3;   // ldmatrix sub-matrix id
    const int mr  = lane & 7;
    const int rr  = lane & 15;

    for (int kc = 0; kc < 16; kc++) {
        int s = kc & 1;
        if (kc + 1 < 16) { issue(kc + 1, s ^ 1); CP_COMMIT(); CP_WAIT1(); }
        else             { CP_WAIT0(); }
        __syncthreads();

        uint32_t st = smb + s * XSTG;
        #pragma unroll
        for (int ks = 0; ks < 2; ks++) {
            uint32_t ah[2][4], al[2][4];
            #pragma unroll
            for (int mf = 0; mf < 2; mf++) {
                int row = mrow + 16 * mf + ((mi & 1) << 3) + mr;
                uint32_t off = row * 64 + ks * 32 + ((mi >> 1) << 4);
                ldsm_x4(ah[mf], st + XAHI + sw64(off));
                ldsm_x4(al[mf], st + XALO + sw64(off));
            }
            #pragma unroll
            for (int nf = 0; nf < 8; nf++) {
                uint32_t bh[2], bl[2];
                int brow = ncol + 8 * nf + (rr & 7);
                uint32_t boff = brow * 64 + ks * 32 + ((rr >> 3) << 4);
                ldsm_x2(bh, st + XBHI + sw64(boff));
                ldsm_x2(bl, st + XBLO + sw64(boff));
                #pragma unroll
                for (int mf = 0; mf < 2; mf++) {
                    mma16816(acc[mf][nf], ah[mf], bh);
                    mma16816(acc[mf][nf], ah[mf], bl);
                    mma16816(acc[mf][nf], al[mf], bh);
                }
            }
        }
        __syncthreads();
    }

    // Epilogue: acc + bias -> g_xz (fp32)
    #pragma unroll
    for (int nf = 0; nf < 8; nf++) {
        int colg = n0 + ncol + 8 * nf + 2 * (lane & 3);
        float2 bv = *(const float2*)(bias + colg);
        #pragma unroll
        for (int mf = 0; mf < 2; mf++) {
            int rowg = m0 + mrow + 16 * mf + (lane >> 2);
            float2 o0 = make_float2(acc[mf][nf][0] + bv.x, acc[mf][nf][1] + bv.y);
            float2 o1 = make_float2(acc[mf][nf][2] + bv.x, acc[mf][nf][3] + bv.y);
            *(float2*)(g_xz + (size_t)rowg * G_ + colg)       = o0;
            *(float2*)(g_xz + (size_t)(rowg + 8) * G_ + colg) = o1;
        }
    }
}

// ---------------------------------------------------------------------------
// One LSTM step via mma.sync.
// Block = 64 batch x 32 z-cols (8 u x 4 gates; nfrag f == gate f).
// 128 threads = 4 warps; warp tile 16m x 32n. K=1024 in 16 chunks of 64
// (128B rows, sw128). Gate fusion fully in-register.
// ---------------------------------------------------------------------------
#define SAHI 0
#define SALO 8192
#define SBHI 16384
#define SBLO 20480
#define SSTG 24576   // one stage (24 KB); 2 stages = 48 KB static smem

__global__ __launch_bounds__(128) void lstm_step_mma(float* __restrict__ out, int t)
{
    __shared__ __align__(1024) char sm[2 * SSTG];
    uint32_t smb = smem_u32(sm);
    const int tid  = threadIdx.x;
    const int wid  = tid >> 5;
    const int lane = tid & 31;
    const int u0 = blockIdx.x * 8;

    const char* hh = (const char*)g_hhi[t & 1];
    const char* hl = (const char*)g_hlo[t & 1];
    const char* rh = (const char*)g_Rt_hi;
    const char* rl = (const char*)g_Rt_lo;

    float acc[4][4] = {};   // [gate][frag]

    auto issue = [&](int kc, int s) {
        uint32_t st = smb + s * SSTG;
        #pragma unroll
        for (int i = 0; i < 4; i++) {      // A hi: 64 rows x 8 granules
            int idx = tid + 128 * i;
            int r = idx >> 3, g = idx & 7;
            CP16(st + SAHI + sw128(r * 128 + g * 16),
                 hh + (size_t)r * 2048 + kc * 128 + g * 16);
        }
        #pragma unroll
        for (int i = 0; i < 4; i++) {      // A lo
            int idx = tid + 128 * i;
            int r = idx >> 3, g = idx & 7;
            CP16(st + SALO + sw128(r * 128 + g * 16),
                 hl + (size_t)r * 2048 + kc * 128 + g * 16);
        }
        #pragma unroll
        for (int i = 0; i < 2; i++) {      // B hi: 32 rows (gathered) x 8 granules
            int idx = tid + 128 * i;
            int c = idx >> 3, g = idx & 7;
            int n = ((c >> 3) << 10) + u0 + (c & 7);   // gate*1024 + u
            CP16(st + SBHI + sw128(c * 128 + g * 16),
                 rh + (size_t)n * 2048 + kc * 128 + g * 16);
        }
        #pragma unroll
        for (int i = 0; i < 2; i++) {      // B lo
            int idx = tid + 128 * i;
            int c = idx >> 3, g = idx & 7;
            int n = ((c >> 3) << 10) + u0 + (c & 7);
            CP16(st + SBLO + sw128(c * 128 + g * 16),
                 rl + (size_t)n * 2048 + kc * 128 + g * 16);
        }
    };

    issue(0, 0); CP_COMMIT();

    const int mi = lane >> 3;
    const int mr = lane & 7;
    const int rr = lane & 15;

    for (int kc = 0; kc < 16; kc++) {
        int s = kc & 1;
        if (kc + 1 < 16) { issue(kc + 1, s ^ 1); CP_COMMIT(); CP_WAIT1(); }
        else             { CP_WAIT0(); }
        __syncthreads();

        uint32_t st = smb + s * SSTG;
        #pragma unroll
        for (int ks = 0; ks < 4; ks++) {
            uint32_t ah[4], al[4];
            int row = 16 * wid + ((mi & 1) << 3) + mr;
            uint32_t off = row * 128 + ks * 32 + ((mi >> 1) << 4);
            ldsm_x4(ah, st + SAHI + sw128(off));
            ldsm_x4(al, st + SALO + sw128(off));
            #pragma unroll
            for (int f = 0; f < 4; f++) {
                uint32_t bh[2], bl[2];
                int brow = 8 * f + (rr & 7);
                uint32_t boff = brow * 128 + ks * 32 + ((rr >> 3) << 4);
                ldsm_x2(bh, st + SBHI + sw128(boff));
                ldsm_x2(bl, st + SBLO + sw128(boff));
                mma16816(acc[f], ah, bh);
                mma16816(acc[f], ah, bl);
                mma16816(acc[f], al, bh);
            }
        }
        __syncthreads();
    }

    // Epilogue: fully in-register gate fusion + state update.
    const int b0 = 16 * wid + (lane >> 2);
    const int uu = u0 + 2 * (lane & 3);
    __nv_bfloat16* nh_hi = g_hhi[(t + 1) & 1];
    __nv_bfloat16* nh_lo = g_hlo[(t + 1) & 1];

    #pragma unroll
    for (int half = 0; half < 2; half++) {
        int b = b0 + 8 * half;
        size_t xb = ((size_t)b * T_ + t) * G_ + uu;
        float2 xi = *(const float2*)(g_xz + xb);
        float2 xf = *(const float2*)(g_xz + xb + 1 * U_);
        float2 xc = *(const float2*)(g_xz + xb + 2 * U_);
        float2 xo = *(const float2*)(g_xz + xb + 3 * U_);
        float2 cc = *(float2*)(g_c + b * U_ + uu);
        float hv[2];
        #pragma unroll
        for (int j = 0; j < 2; j++) {
            int a = 2 * half + j;
            float zi = acc[0][a] + (j ? xi.y : xi.x);
            float zf = acc[1][a] + (j ? xf.y : xf.x);
            float zc = acc[2][a] + (j ? xc.y : xc.x);
            float zo = acc[3][a] + (j ? xo.y : xo.x);
            float ig = 1.0f / (1.0f + __expf(-zi));
            float fg = 1.0f / (1.0f + __expf(-zf));
            float og = 1.0f / (1.0f + __expf(-zo));
            float cp = j ? cc.y : cc.x;
            float cn = fg * cp + ig * tanhf(zc);
            if (j) cc.y = cn; else cc.x = cn;
            hv[j] = og * tanhf(cn);
        }
        *(float2*)(g_c + b * U_ + uu) = cc;
        if (t == T_ - 1) {
            *(float2*)(out + b * U_ + uu) = make_float2(hv[0], hv[1]);
        } else {
            __nv_bfloat16 h0 = __float2bfloat16(hv[0]);
            __nv_bfloat16 h1 = __float2bfloat16(hv[1]);
            *(__nv_bfloat162*)(nh_hi + b * U_ + uu) = __halves2bfloat162(h0, h1);
            *(__nv_bfloat162*)(nh_lo + b * U_ + uu) = __halves2bfloat162(
                __float2bfloat16(hv[0] - __bfloat162float(h0)),
                __float2bfloat16(hv[1] - __bfloat162float(h1)));
        }
    }
}

// ---------------------------------------------------------------------------
extern "C" void kernel_launch(void* const* d_in, const int* in_sizes, int n_in,
                              void* d_out, int out_size)
{
    const float* x    = (const float*)d_in[0];   // [64, 512, 512]
    const float* W    = (const float*)d_in[1];   // [512, 4096]
    const float* R    = (const float*)d_in[2];   // [1024, 4096]
    const float* bias = (const float*)d_in[3];   // [4096]
    float* out = (float*)d_out;                  // [64, 1024]

    cudaFuncSetAttribute(gemm_xz_mma,
                         cudaFuncAttributeMaxDynamicSharedMemorySize, 2 * XSTG);

    init_state<<<256, 256>>>();
    split_x<<<(B_ * T_ * D_ / 4 + 255) / 256, 256>>>(x);
    transpose_split_sel<<<dim3(G_ / 32, D_ / 32), dim3(32, 8)>>>(W, 0, D_, G_);
    transpose_split_sel<<<dim3(G_ / 32, U_ / 32), dim3(32, 8)>>>(R, 1, U_, G_);
    gemm_xz_mma<<<dim3(G_ / 128, (B_ * T_) / 128), 256, 2 * XSTG>>>(bias);
    for (int t = 0; t < T_; t++) {
        lstm_step_mma<<<128, 128>>>(out, t);
    }
}